// round 8
// baseline (speedup 1.0000x reference)
#include <cuda_runtime.h>
#include <cuda_bf16.h>

// ---------------------------------------------------------------------------
// HilbertSerialization: 2M points -> 26-bit Hilbert+batch code -> stable argsort
// Output dtype: FLOAT32 (indices as float; all < 2^24, exact).
// 3-pass stable LSD radix sort (9,9,8 bits), 256-thread tiles of 4096 with
// smem permute for coalesced scatter. Pass 1 values are implicit (val = index).
// All graph-capturable, zero allocations (static __device__ scratch).
// ---------------------------------------------------------------------------

#define HS_MAXN   2000000
#define TILE      4096
#define THREADS   256
#define NWARP     (THREADS / 32)                  // 8
#define IPT       (TILE / THREADS)                // 16
#define MAXBINS   512
#define NBLK_MAX  ((HS_MAXN + TILE - 1) / TILE)   // 489

__device__ unsigned int g_keys_a[HS_MAXN];
__device__ unsigned int g_keys_b[HS_MAXN];
__device__ unsigned int g_vals_a[HS_MAXN];
__device__ unsigned int g_vals_b[HS_MAXN];
__device__ unsigned int g_counts[MAXBINS * NBLK_MAX];
__device__ unsigned int g_rowtot[MAXBINS];
__device__ unsigned int g_rowbase[MAXBINS];
__device__ int g_coords64;

// ---------------------------------------------------------------------------
// Encode (keys only; values are implicit in pass 1)
// ---------------------------------------------------------------------------
__global__ void detect_dtype_kernel(const unsigned int* __restrict__ w, int nwords)
{
    __shared__ int ok;
    if (threadIdx.x == 0) ok = 1;
    __syncthreads();
    for (int i = 2 * threadIdx.x + 1; i < nwords; i += 2 * blockDim.x) {
        if (w[i] != 0u) { ok = 0; break; }
    }
    __syncthreads();
    if (threadIdx.x == 0) g_coords64 = ok;
}

__global__ void __launch_bounds__(256)
hilbert_encode_kernel(const unsigned int* __restrict__ coords,
                      const unsigned int* __restrict__ ss,
                      const unsigned int* __restrict__ shifts,
                      unsigned int* __restrict__ keys,
                      int n)
{
    int i = blockIdx.x * blockDim.x + threadIdx.x;
    if (i >= n) return;

    unsigned int b, zc, yc, xc;                  // coords row = [b, z, y, x]
    if (g_coords64) {
        const unsigned int* p = coords + (size_t)i * 8;   // int64 stride
        b = p[0]; zc = p[2]; yc = p[4]; xc = p[6];
    } else {
        uint4 c = reinterpret_cast<const uint4*>(coords)[i];
        b = c.x; zc = c.y; yc = c.z; xc = c.w;
    }

    int D, H, W;                                 // sparse_shape = [D, H, W]
    if (ss[1] == 0u) { D = (int)ss[0]; H = (int)ss[2]; W = (int)ss[4]; }
    else             { D = (int)ss[0]; H = (int)ss[1]; W = (int)ss[2]; }

    bool sh = (shifts[0] != 0u);
    int sx = sh ? 15 : 0, sy = sh ? 15 : 0, sz = sh ? 4 : 0;

    unsigned int x = (unsigned int)(((int)xc + sx) % W);
    unsigned int y = (unsigned int)(((int)yc + sy) % H);
    unsigned int z = (unsigned int)(((int)zc + sz) % D);

    // Literal transcription of reference hilbert_encode (DEPTH=8).
    bool gray[3][8];
    unsigned int loc[3] = { x, y, z };
    #pragma unroll
    for (int dim = 0; dim < 3; ++dim)
        #pragma unroll
        for (int bit = 0; bit < 8; ++bit)
            gray[dim][bit] = ((loc[dim] >> (7 - bit)) & 1u) != 0u;

    #pragma unroll
    for (int bit = 0; bit < 8; ++bit) {
        #pragma unroll
        for (int dim = 0; dim < 3; ++dim) {
            bool mask = gray[dim][bit];
            for (int j = bit + 1; j < 8; ++j)
                gray[0][j] = gray[0][j] != mask;
            for (int j = bit + 1; j < 8; ++j) {
                bool to_flip = (!mask) && (gray[0][j] != gray[dim][j]);
                gray[dim][j] = gray[dim][j] != to_flip;
                gray[0][j]   = gray[0][j]   != to_flip;
            }
        }
    }

    unsigned int h = 0;
    #pragma unroll
    for (int bit = 0; bit < 8; ++bit)
        #pragma unroll
        for (int dim = 0; dim < 3; ++dim)
            h = (h << 1) | (gray[dim][bit] ? 1u : 0u);

    h ^= h >> 16; h ^= h >> 8; h ^= h >> 4; h ^= h >> 2; h ^= h >> 1;

    keys[i] = h | (b << 24);                     // code | b << DEPTH*3
}

// ---------------------------------------------------------------------------
// Block exclusive scan (THREADS threads, NWARP warps). ws holds NWARP+1 uints.
// ---------------------------------------------------------------------------
__device__ __forceinline__ unsigned int block_exscan(unsigned int v,
                                                     unsigned int* ws,
                                                     unsigned int* total)
{
    int lane = threadIdx.x & 31, wid = threadIdx.x >> 5;
    unsigned int inc = v;
    #pragma unroll
    for (int o = 1; o < 32; o <<= 1) {
        unsigned int u = __shfl_up_sync(~0u, inc, o);
        if (lane >= o) inc += u;
    }
    __syncthreads();
    if (lane == 31) ws[wid] = inc;
    __syncthreads();
    if (threadIdx.x == 0) {
        unsigned int s = 0;
        #pragma unroll
        for (int i = 0; i < NWARP; ++i) { unsigned int t = ws[i]; ws[i] = s; s += t; }
        ws[NWARP] = s;
    }
    __syncthreads();
    if (total) *total = ws[NWARP];
    return inc - v + ws[wid];
}

// ---------------------------------------------------------------------------
// Histogram
// ---------------------------------------------------------------------------
template<int SHIFT, int BITS>
__global__ void __launch_bounds__(THREADS)
histo_kernel(const unsigned int* __restrict__ keys,
             unsigned int* __restrict__ counts, int n, int nblocks)
{
    const int NBINS = 1 << BITS;
    __shared__ unsigned int h[NBINS];
    for (int i = threadIdx.x; i < NBINS; i += THREADS) h[i] = 0;
    __syncthreads();
    int start = blockIdx.x * TILE;
    int lane = threadIdx.x & 31;
    for (int i = threadIdx.x; i < TILE; i += THREADS) {
        int g = start + i;
        bool act = (g < n);
        unsigned int amask = __ballot_sync(~0u, act);
        if (act) {
            unsigned int d = (keys[g] >> SHIFT) & (NBINS - 1);
            unsigned int peers = __match_any_sync(amask, d);
            if (lane == (__ffs(peers) - 1))
                atomicAdd(&h[d], (unsigned int)__popc(peers));
        }
    }
    __syncthreads();
    for (int i = threadIdx.x; i < NBINS; i += THREADS)
        counts[(size_t)i * nblocks + blockIdx.x] = h[i];
}

// ---------------------------------------------------------------------------
// Scans (counts row-major exclusive + digit-base exclusive)
// ---------------------------------------------------------------------------
__global__ void __launch_bounds__(THREADS)
scan_rows_kernel(unsigned int* __restrict__ counts,
                 unsigned int* __restrict__ rowtot, int nblocks)
{
    __shared__ unsigned int ws[NWARP + 1];
    unsigned int* row = counts + (size_t)blockIdx.x * nblocks;
    int base = threadIdx.x * 2;                   // 256*2 = 512 >= 489
    unsigned int v[2], s = 0;
    #pragma unroll
    for (int j = 0; j < 2; ++j) {
        int i = base + j;
        v[j] = (i < nblocks) ? row[i] : 0u;
        s += v[j];
    }
    unsigned int total;
    unsigned int run = block_exscan(s, ws, &total);
    #pragma unroll
    for (int j = 0; j < 2; ++j) {
        int i = base + j;
        if (i < nblocks) row[i] = run;
        run += v[j];
    }
    if (threadIdx.x == 0) rowtot[blockIdx.x] = total;
}

__global__ void __launch_bounds__(THREADS)
scan_base_kernel(const unsigned int* __restrict__ rowtot,
                 unsigned int* __restrict__ rowbase, int nbins)
{
    __shared__ unsigned int ws[NWARP + 1];
    int base = threadIdx.x * 2;
    unsigned int v[2], s = 0;
    #pragma unroll
    for (int j = 0; j < 2; ++j) {
        int i = base + j;
        v[j] = (i < nbins) ? rowtot[i] : 0u;
        s += v[j];
    }
    unsigned int run = block_exscan(s, ws, 0);
    #pragma unroll
    for (int j = 0; j < 2; ++j) {
        int i = base + j;
        if (i < nbins) rowbase[i] = run;
        run += v[j];
    }
}

// ---------------------------------------------------------------------------
// Stable scatter with smem permute for coalesced output.
// FIRST=1: vals are implicit (val = global index), no vals_in read.
// FINAL=1: write float(val) to outf, skip key write.
// ---------------------------------------------------------------------------
template<int SHIFT, int BITS, int FIRST, int FINAL>
__global__ void __launch_bounds__(THREADS)
scatter_kernel(const unsigned int* __restrict__ keys_in,
               const unsigned int* __restrict__ vals_in,
               unsigned int* __restrict__ keys_out,
               unsigned int* __restrict__ vals_out,
               float* __restrict__ outf,
               const unsigned int* __restrict__ counts,   // row-scanned
               const unsigned int* __restrict__ rowbase,
               int n, int nblocks)
{
    const int NBINS = 1 << BITS;
    __shared__ unsigned short cnt[NBINS][NWARP];   // [digit][warp]
    __shared__ unsigned int dpref[NBINS];
    __shared__ unsigned int gbase[NBINS];
    __shared__ unsigned int skeys[TILE];           // tile-sorted keys
    __shared__ unsigned int svals[TILE];           // tile-sorted vals
    __shared__ unsigned int ws[NWARP + 1];

    int t = threadIdx.x, lane = t & 31, w = t >> 5;
    int start = blockIdx.x * TILE;
    int tile_n = n - start; if (tile_n > TILE) tile_n = TILE;

    unsigned int* cnt32 = (unsigned int*)&cnt[0][0];
    for (int i = t; i < NBINS * (NWARP / 2); i += THREADS) cnt32[i] = 0;
    for (int d = t; d < NBINS; d += THREADS)
        gbase[d] = counts[(size_t)d * nblocks + blockIdx.x] + rowbase[d];

    // Load keys (warp-blocked tile order; coalesced) into registers.
    unsigned int k[IPT];
    bool act[IPT];
    #pragma unroll
    for (int q = 0; q < IPT; ++q) {
        int i = w * (32 * IPT) + q * 32 + lane;
        int g = start + i;
        act[q] = (g < n);
        k[q] = act[q] ? keys_in[g] : 0u;
    }
    __syncthreads();

    // Phase 1: per-warp histogram (match-aggregated).
    #pragma unroll
    for (int q = 0; q < IPT; ++q) {
        unsigned int amask = __ballot_sync(~0u, act[q]);
        if (act[q]) {
            unsigned int d = (k[q] >> SHIFT) & (NBINS - 1);
            unsigned int peers = __match_any_sync(amask, d);
            if (lane == (__ffs(peers) - 1))
                cnt[d][w] = (unsigned short)(cnt[d][w] + __popc(peers));
        }
    }
    __syncthreads();

    // Flat exclusive scan of cnt in (digit, warp) order.
    {
        unsigned short* flat = &cnt[0][0];
        const int E = (NBINS * NWARP) / THREADS;   // 16 (BITS=9) / 8 (BITS=8)
        unsigned int loc[16], s = 0;
        #pragma unroll
        for (int j = 0; j < E; ++j) { loc[j] = flat[t * E + j]; s += loc[j]; }
        unsigned int run = block_exscan(s, ws, 0);
        #pragma unroll
        for (int j = 0; j < E; ++j) {
            flat[t * E + j] = (unsigned short)run;
            run += loc[j];
        }
    }
    __syncthreads();
    for (int d = t; d < NBINS; d += THREADS) dpref[d] = cnt[d][0];
    __syncthreads();

    // Phase 2: stable rank -> write (key,val) into tile-sorted smem position.
    #pragma unroll
    for (int q = 0; q < IPT; ++q) {
        int i = w * (32 * IPT) + q * 32 + lane;
        int g = start + i;
        unsigned int amask = __ballot_sync(~0u, act[q]);
        if (act[q]) {
            unsigned int d = (k[q] >> SHIFT) & (NBINS - 1);
            unsigned int peers = __match_any_sync(amask, d);
            int leader = __ffs(peers) - 1;
            unsigned int base = 0;
            if (lane == leader) {
                base = cnt[d][w];
                cnt[d][w] = (unsigned short)(base + __popc(peers));
            }
            base = __shfl_sync(peers, base, leader);
            unsigned int rank = base + __popc(peers & ((1u << lane) - 1u));
            skeys[rank] = k[q];
            svals[rank] = FIRST ? (unsigned int)g : vals_in[g];
        }
    }
    __syncthreads();

    // Output: tile-sorted order -> near-coalesced global writes.
    for (int j = t; j < tile_n; j += THREADS) {
        unsigned int key = skeys[j];
        unsigned int d = (key >> SHIFT) & (NBINS - 1);
        unsigned int pos = gbase[d] + (unsigned int)j - dpref[d];
        if (FINAL) {
            outf[pos] = (float)svals[j];
        } else {
            keys_out[pos] = key;
            vals_out[pos] = svals[j];
        }
    }
}

// ---------------------------------------------------------------------------
// Host
// ---------------------------------------------------------------------------
template<int SHIFT, int BITS, int FIRST, int FINAL>
static void radix_pass(const unsigned int* ki, const unsigned int* vi,
                       unsigned int* ko, unsigned int* vo, float* outf,
                       unsigned int* counts, unsigned int* rowtot,
                       unsigned int* rowbase, int n, int nblocks)
{
    const int NBINS = 1 << BITS;
    histo_kernel<SHIFT, BITS><<<nblocks, THREADS>>>(ki, counts, n, nblocks);
    scan_rows_kernel<<<NBINS, THREADS>>>(counts, rowtot, nblocks);
    scan_base_kernel<<<1, THREADS>>>(rowtot, rowbase, NBINS);
    scatter_kernel<SHIFT, BITS, FIRST, FINAL><<<nblocks, THREADS>>>(
        ki, vi, ko, vo, outf, counts, rowbase, n, nblocks);
}

extern "C" void kernel_launch(void* const* d_in, const int* in_sizes, int n_in,
                              void* d_out, int out_size)
{
    // Identify inputs by size signature.
    int ci = 0;
    for (int i = 1; i < n_in; ++i)
        if (in_sizes[i] > in_sizes[ci]) ci = i;
    int si = -1, hi = -1;
    for (int i = 0; i < n_in; ++i) {
        if (i == ci) continue;
        if (si < 0) { si = i; continue; }
        if (hi < 0) { hi = i; continue; }
    }
    if (hi >= 0 && in_sizes[hi] > in_sizes[si]) { int tq = si; si = hi; hi = tq; }
    if (si < 0) si = ci;
    if (hi < 0) hi = si;

    const unsigned int* coords = (const unsigned int*)d_in[ci];
    const unsigned int* ss     = (const unsigned int*)d_in[si];
    const unsigned int* shifts = (const unsigned int*)d_in[hi];

    int n = out_size;
    if (n > HS_MAXN) n = HS_MAXN;
    if (n <= 0) return;

    unsigned int *ka, *kb, *va, *vb, *counts, *rowtot, *rowbase;
    cudaGetSymbolAddress((void**)&ka, g_keys_a);
    cudaGetSymbolAddress((void**)&kb, g_keys_b);
    cudaGetSymbolAddress((void**)&va, g_vals_a);
    cudaGetSymbolAddress((void**)&vb, g_vals_b);
    cudaGetSymbolAddress((void**)&counts, g_counts);
    cudaGetSymbolAddress((void**)&rowtot, g_rowtot);
    cudaGetSymbolAddress((void**)&rowbase, g_rowbase);

    detect_dtype_kernel<<<1, 256>>>(coords, 4096);

    int eblocks = (n + 255) / 256;
    hilbert_encode_kernel<<<eblocks, 256>>>(coords, ss, shifts, ka, n);

    int nblocks = (n + TILE - 1) / TILE;
    radix_pass<0,  9, 1, 0>(ka, 0,  kb, vb, 0, counts, rowtot, rowbase, n, nblocks);
    radix_pass<9,  9, 0, 0>(kb, vb, ka, va, 0, counts, rowtot, rowbase, n, nblocks);
    radix_pass<18, 8, 0, 1>(ka, va, 0, 0, (float*)d_out,
                            counts, rowtot, rowbase, n, nblocks);
}

// round 9
// speedup vs baseline: 1.0510x; 1.0510x over previous
#include <cuda_runtime.h>
#include <cuda_bf16.h>

// ---------------------------------------------------------------------------
// HilbertSerialization: 2M points -> 26-bit Hilbert+batch code -> stable argsort
// Output dtype: FLOAT32 (indices as float; all < 2^24, exact).
// 3-pass stable LSD radix sort (9,9,8 bits), 256-thread tiles of 4096,
// direct register-based scatter with (key,val) packed as uint2 (STG.64).
// Pass 1 values are implicit (val = index). Packed-integer Hilbert encode.
// All graph-capturable, zero allocations (static __device__ scratch).
// ---------------------------------------------------------------------------

#define HS_MAXN   2000000
#define TILE      4096
#define THREADS   256
#define NWARP     (THREADS / 32)                  // 8
#define IPT       (TILE / THREADS)                // 16
#define MAXBINS   512
#define NBLK_MAX  ((HS_MAXN + TILE - 1) / TILE)   // 489

__device__ unsigned int g_keys[HS_MAXN];          // encode output (pass-1 input)
__device__ uint2        g_pairs_a[HS_MAXN];       // (key, val) ping
__device__ uint2        g_pairs_b[HS_MAXN];       // (key, val) pong
__device__ unsigned int g_counts[MAXBINS * NBLK_MAX];
__device__ unsigned int g_rowtot[MAXBINS];
__device__ unsigned int g_rowbase[MAXBINS];
__device__ int g_coords64;

// ---------------------------------------------------------------------------
// Encode (packed-integer form of the reference boolean-array algorithm).
// gray bit `bit` (0=MSB) lives at integer bit (7-bit); "bits below" = low mask.
// ---------------------------------------------------------------------------
__global__ void detect_dtype_kernel(const unsigned int* __restrict__ w, int nwords)
{
    __shared__ int ok;
    if (threadIdx.x == 0) ok = 1;
    __syncthreads();
    for (int i = 2 * threadIdx.x + 1; i < nwords; i += 2 * blockDim.x) {
        if (w[i] != 0u) { ok = 0; break; }
    }
    __syncthreads();
    if (threadIdx.x == 0) g_coords64 = ok;
}

__global__ void __launch_bounds__(256)
hilbert_encode_kernel(const unsigned int* __restrict__ coords,
                      const unsigned int* __restrict__ ss,
                      const unsigned int* __restrict__ shifts,
                      unsigned int* __restrict__ keys,
                      int n)
{
    int i = blockIdx.x * blockDim.x + threadIdx.x;
    if (i >= n) return;

    unsigned int b, zc, yc, xc;                  // coords row = [b, z, y, x]
    if (g_coords64) {
        const unsigned int* p = coords + (size_t)i * 8;   // int64 stride
        b = p[0]; zc = p[2]; yc = p[4]; xc = p[6];
    } else {
        uint4 c = reinterpret_cast<const uint4*>(coords)[i];
        b = c.x; zc = c.y; yc = c.z; xc = c.w;
    }

    int D, H, W;                                 // sparse_shape = [D, H, W]
    if (ss[1] == 0u) { D = (int)ss[0]; H = (int)ss[2]; W = (int)ss[4]; }
    else             { D = (int)ss[0]; H = (int)ss[1]; W = (int)ss[2]; }

    bool sh = (shifts[0] != 0u);
    int sx = sh ? 15 : 0, sy = sh ? 15 : 0, sz = sh ? 4 : 0;

    unsigned int x = (unsigned int)(((int)xc + sx) % W);
    unsigned int y = (unsigned int)(((int)yc + sy) % H);
    unsigned int z = (unsigned int)(((int)zc + sz) % D);

    unsigned int g0 = x & 0xFFu;                 // locs = [x, y, z]
    unsigned int g1 = y & 0xFFu;
    unsigned int g2 = z & 0xFFu;

    // Axes -> transposed-gray transform. For each (bit, dim) in order:
    //   m = gray[dim][bit];  if m: g0 ^= low;  else: f=(g0^gdim)&low; both ^= f
    #pragma unroll
    for (int bit = 0; bit < 8; ++bit) {
        unsigned int low = (1u << (7 - bit)) - 1u;
        // dim 0
        {
            unsigned int m = (g0 >> (7 - bit)) & 1u;
            if (m) g0 ^= low;                    // dim==0: f==0 when m==0
        }
        // dim 1
        {
            unsigned int m = (g1 >> (7 - bit)) & 1u;
            if (m) { g0 ^= low; }
            else   { unsigned int f = (g0 ^ g1) & low; g1 ^= f; g0 ^= f; }
        }
        // dim 2
        {
            unsigned int m = (g2 >> (7 - bit)) & 1u;
            if (m) { g0 ^= low; }
            else   { unsigned int f = (g0 ^ g2) & low; g2 ^= f; g0 ^= f; }
        }
    }

    // Interleave bit-major, dim-minor, MSB first -> 24-bit gray code.
    unsigned int h = 0;
    #pragma unroll
    for (int bit = 7; bit >= 0; --bit) {
        h = (h << 3)
          | (((g0 >> bit) & 1u) << 2)
          | (((g1 >> bit) & 1u) << 1)
          |  ((g2 >> bit) & 1u);
    }

    // gray -> binary (prefix XOR; matches _gray2binary shifts 16,8,4,2,1).
    h ^= h >> 16; h ^= h >> 8; h ^= h >> 4; h ^= h >> 2; h ^= h >> 1;

    keys[i] = h | (b << 24);                     // code | b << DEPTH*3
}

// ---------------------------------------------------------------------------
// Block exclusive scan (THREADS threads, NWARP warps). ws holds NWARP+1 uints.
// ---------------------------------------------------------------------------
__device__ __forceinline__ unsigned int block_exscan(unsigned int v,
                                                     unsigned int* ws,
                                                     unsigned int* total)
{
    int lane = threadIdx.x & 31, wid = threadIdx.x >> 5;
    unsigned int inc = v;
    #pragma unroll
    for (int o = 1; o < 32; o <<= 1) {
        unsigned int u = __shfl_up_sync(~0u, inc, o);
        if (lane >= o) inc += u;
    }
    __syncthreads();
    if (lane == 31) ws[wid] = inc;
    __syncthreads();
    if (threadIdx.x == 0) {
        unsigned int s = 0;
        #pragma unroll
        for (int i = 0; i < NWARP; ++i) { unsigned int t = ws[i]; ws[i] = s; s += t; }
        ws[NWARP] = s;
    }
    __syncthreads();
    if (total) *total = ws[NWARP];
    return inc - v + ws[wid];
}

// ---------------------------------------------------------------------------
// Histogram. STRIDE=1: plain key array. STRIDE=2: key = .x of uint2 pairs.
// ---------------------------------------------------------------------------
template<int SHIFT, int BITS, int STRIDE>
__global__ void __launch_bounds__(THREADS)
histo_kernel(const unsigned int* __restrict__ keys,
             unsigned int* __restrict__ counts, int n, int nblocks)
{
    const int NBINS = 1 << BITS;
    __shared__ unsigned int h[NBINS];
    for (int i = threadIdx.x; i < NBINS; i += THREADS) h[i] = 0;
    __syncthreads();
    int start = blockIdx.x * TILE;
    int lane = threadIdx.x & 31;
    for (int i = threadIdx.x; i < TILE; i += THREADS) {
        int g = start + i;
        bool act = (g < n);
        unsigned int amask = __ballot_sync(~0u, act);
        if (act) {
            unsigned int d = (keys[(size_t)g * STRIDE] >> SHIFT) & (NBINS - 1);
            unsigned int peers = __match_any_sync(amask, d);
            if (lane == (__ffs(peers) - 1))
                atomicAdd(&h[d], (unsigned int)__popc(peers));
        }
    }
    __syncthreads();
    for (int i = threadIdx.x; i < NBINS; i += THREADS)
        counts[(size_t)i * nblocks + blockIdx.x] = h[i];
}

// ---------------------------------------------------------------------------
// Scans
// ---------------------------------------------------------------------------
__global__ void __launch_bounds__(THREADS)
scan_rows_kernel(unsigned int* __restrict__ counts,
                 unsigned int* __restrict__ rowtot, int nblocks)
{
    __shared__ unsigned int ws[NWARP + 1];
    unsigned int* row = counts + (size_t)blockIdx.x * nblocks;
    int base = threadIdx.x * 2;                   // 256*2 = 512 >= 489
    unsigned int v[2], s = 0;
    #pragma unroll
    for (int j = 0; j < 2; ++j) {
        int i = base + j;
        v[j] = (i < nblocks) ? row[i] : 0u;
        s += v[j];
    }
    unsigned int total;
    unsigned int run = block_exscan(s, ws, &total);
    #pragma unroll
    for (int j = 0; j < 2; ++j) {
        int i = base + j;
        if (i < nblocks) row[i] = run;
        run += v[j];
    }
    if (threadIdx.x == 0) rowtot[blockIdx.x] = total;
}

__global__ void __launch_bounds__(THREADS)
scan_base_kernel(const unsigned int* __restrict__ rowtot,
                 unsigned int* __restrict__ rowbase, int nbins)
{
    __shared__ unsigned int ws[NWARP + 1];
    int base = threadIdx.x * 2;
    unsigned int v[2], s = 0;
    #pragma unroll
    for (int j = 0; j < 2; ++j) {
        int i = base + j;
        v[j] = (i < nbins) ? rowtot[i] : 0u;
        s += v[j];
    }
    unsigned int run = block_exscan(s, ws, 0);
    #pragma unroll
    for (int j = 0; j < 2; ++j) {
        int i = base + j;
        if (i < nbins) rowbase[i] = run;
        run += v[j];
    }
}

// ---------------------------------------------------------------------------
// Stable direct scatter (registers -> scattered global writes).
// FIRST=1: input is plain key array; val = global index; output uint2 pairs.
// FINAL=1: input is uint2 pairs; output is float(val) only.
// Otherwise: uint2 pairs in, uint2 pairs out.
// ---------------------------------------------------------------------------
template<int SHIFT, int BITS, int FIRST, int FINAL>
__global__ void __launch_bounds__(THREADS)
scatter_kernel(const unsigned int* __restrict__ keys_in,   // FIRST only
               const uint2* __restrict__ pairs_in,         // !FIRST
               uint2* __restrict__ pairs_out,              // !FINAL
               float* __restrict__ outf,                   // FINAL
               const unsigned int* __restrict__ counts,    // row-scanned
               const unsigned int* __restrict__ rowbase,
               int n, int nblocks)
{
    const int NBINS = 1 << BITS;
    __shared__ unsigned short cnt[NBINS][NWARP];   // [digit][warp]
    __shared__ unsigned int dpref[NBINS];
    __shared__ unsigned int gbase[NBINS];
    __shared__ unsigned int ws[NWARP + 1];

    int t = threadIdx.x, lane = t & 31, w = t >> 5;
    int start = blockIdx.x * TILE;

    unsigned int* cnt32 = (unsigned int*)&cnt[0][0];
    for (int i = t; i < NBINS * (NWARP / 2); i += THREADS) cnt32[i] = 0;
    for (int d = t; d < NBINS; d += THREADS)
        gbase[d] = counts[(size_t)d * nblocks + blockIdx.x] + rowbase[d];

    // Load (key,val) into registers, warp-blocked tile order (coalesced).
    unsigned int k[IPT], v[IPT];
    bool act[IPT];
    #pragma unroll
    for (int q = 0; q < IPT; ++q) {
        int i = w * (32 * IPT) + q * 32 + lane;
        int g = start + i;
        act[q] = (g < n);
        if (act[q]) {
            if (FIRST) { k[q] = keys_in[g]; v[q] = (unsigned int)g; }
            else       { uint2 p = pairs_in[g]; k[q] = p.x; v[q] = p.y; }
        } else { k[q] = 0u; v[q] = 0u; }
    }
    __syncthreads();

    // Phase 1: per-warp histogram (match-aggregated).
    #pragma unroll
    for (int q = 0; q < IPT; ++q) {
        unsigned int amask = __ballot_sync(~0u, act[q]);
        if (act[q]) {
            unsigned int d = (k[q] >> SHIFT) & (NBINS - 1);
            unsigned int peers = __match_any_sync(amask, d);
            if (lane == (__ffs(peers) - 1))
                cnt[d][w] = (unsigned short)(cnt[d][w] + __popc(peers));
        }
    }
    __syncthreads();

    // Flat exclusive scan of cnt in (digit, warp) order.
    {
        unsigned short* flat = &cnt[0][0];
        const int E = (NBINS * NWARP) / THREADS;   // 16 (BITS=9) / 8 (BITS=8)
        unsigned int loc[16], s = 0;
        #pragma unroll
        for (int j = 0; j < E; ++j) { loc[j] = flat[t * E + j]; s += loc[j]; }
        unsigned int run = block_exscan(s, ws, 0);
        #pragma unroll
        for (int j = 0; j < E; ++j) {
            flat[t * E + j] = (unsigned short)run;
            run += loc[j];
        }
    }
    __syncthreads();
    for (int d = t; d < NBINS; d += THREADS) dpref[d] = cnt[d][0];
    __syncthreads();

    // Phase 2: stable rank -> direct scattered write.
    #pragma unroll
    for (int q = 0; q < IPT; ++q) {
        unsigned int amask = __ballot_sync(~0u, act[q]);
        if (act[q]) {
            unsigned int d = (k[q] >> SHIFT) & (NBINS - 1);
            unsigned int peers = __match_any_sync(amask, d);
            int leader = __ffs(peers) - 1;
            unsigned int base = 0;
            if (lane == leader) {
                base = cnt[d][w];
                cnt[d][w] = (unsigned short)(base + __popc(peers));
            }
            base = __shfl_sync(peers, base, leader);
            unsigned int rank = base + __popc(peers & ((1u << lane) - 1u));
            unsigned int pos = gbase[d] + rank - dpref[d];
            if (FINAL) outf[pos] = (float)v[q];
            else       pairs_out[pos] = make_uint2(k[q], v[q]);
        }
    }
}

// ---------------------------------------------------------------------------
// Host
// ---------------------------------------------------------------------------
extern "C" void kernel_launch(void* const* d_in, const int* in_sizes, int n_in,
                              void* d_out, int out_size)
{
    // Identify inputs by size signature.
    int ci = 0;
    for (int i = 1; i < n_in; ++i)
        if (in_sizes[i] > in_sizes[ci]) ci = i;
    int si = -1, hi = -1;
    for (int i = 0; i < n_in; ++i) {
        if (i == ci) continue;
        if (si < 0) { si = i; continue; }
        if (hi < 0) { hi = i; continue; }
    }
    if (hi >= 0 && in_sizes[hi] > in_sizes[si]) { int tq = si; si = hi; hi = tq; }
    if (si < 0) si = ci;
    if (hi < 0) hi = si;

    const unsigned int* coords = (const unsigned int*)d_in[ci];
    const unsigned int* ss     = (const unsigned int*)d_in[si];
    const unsigned int* shifts = (const unsigned int*)d_in[hi];

    int n = out_size;
    if (n > HS_MAXN) n = HS_MAXN;
    if (n <= 0) return;

    unsigned int *ka, *counts, *rowtot, *rowbase;
    uint2 *pa, *pb;
    cudaGetSymbolAddress((void**)&ka, g_keys);
    cudaGetSymbolAddress((void**)&pa, g_pairs_a);
    cudaGetSymbolAddress((void**)&pb, g_pairs_b);
    cudaGetSymbolAddress((void**)&counts, g_counts);
    cudaGetSymbolAddress((void**)&rowtot, g_rowtot);
    cudaGetSymbolAddress((void**)&rowbase, g_rowbase);

    detect_dtype_kernel<<<1, 256>>>(coords, 4096);

    int eblocks = (n + 255) / 256;
    hilbert_encode_kernel<<<eblocks, 256>>>(coords, ss, shifts, ka, n);

    int nblocks = (n + TILE - 1) / TILE;

    // Pass 1: bits [0,9), plain keys -> pairs_b
    histo_kernel<0, 9, 1><<<nblocks, THREADS>>>(ka, counts, n, nblocks);
    scan_rows_kernel<<<512, THREADS>>>(counts, rowtot, nblocks);
    scan_base_kernel<<<1, THREADS>>>(rowtot, rowbase, 512);
    scatter_kernel<0, 9, 1, 0><<<nblocks, THREADS>>>(
        ka, 0, pb, 0, counts, rowbase, n, nblocks);

    // Pass 2: bits [9,18), pairs_b -> pairs_a
    histo_kernel<9, 9, 2><<<nblocks, THREADS>>>((const unsigned int*)pb,
                                                counts, n, nblocks);
    scan_rows_kernel<<<512, THREADS>>>(counts, rowtot, nblocks);
    scan_base_kernel<<<1, THREADS>>>(rowtot, rowbase, 512);
    scatter_kernel<9, 9, 0, 0><<<nblocks, THREADS>>>(
        0, pb, pa, 0, counts, rowbase, n, nblocks);

    // Pass 3: bits [18,26), pairs_a -> float out
    histo_kernel<18, 8, 2><<<nblocks, THREADS>>>((const unsigned int*)pa,
                                                 counts, n, nblocks);
    scan_rows_kernel<<<256, THREADS>>>(counts, rowtot, nblocks);
    scan_base_kernel<<<1, THREADS>>>(rowtot, rowbase, 256);
    scatter_kernel<18, 8, 0, 1><<<nblocks, THREADS>>>(
        0, pa, 0, (float*)d_out, counts, rowbase, n, nblocks);
}